// round 2
// baseline (speedup 1.0000x reference)
#include <cuda_runtime.h>
#include <cstdint>
#include <math.h>

// ---------------- problem constants ----------------
#define B_    4
#define NQ_   2048
#define NK_   2048
#define DM    512
#define NH    8
#define DH    64
#define MTOT  (B_*NQ_)          // 8192 rows

// ---------------- scratch (device globals; no allocations allowed) --------
__device__ float g_q [B_*NQ_*DM];
__device__ float g_k [B_*NK_*DM];
__device__ float g_v [B_*NK_*DM];
__device__ float g_h0[B_*NQ_*DM];   // attention out + q residual (pre-LN0)
__device__ float g_h1[B_*NQ_*DM];   // post-LN0
__device__ float g_h2[B_*NQ_*DM];   // H1 + relu(H1 Wo + bo) (pre-LN1)

// ---------------- tf32 helpers ----------------
__device__ __forceinline__ unsigned f2tf(float x){
    unsigned u; asm("cvt.rna.tf32.f32 %0, %1;" : "=r"(u) : "f"(x)); return u;
}
__device__ __forceinline__ void mma_tf32(float* c, const unsigned* a, const unsigned* b){
    asm volatile("mma.sync.aligned.m16n8k8.row.col.f32.tf32.tf32.f32 "
        "{%0,%1,%2,%3}, {%4,%5,%6,%7}, {%8,%9}, {%0,%1,%2,%3};\n"
        : "+f"(c[0]), "+f"(c[1]), "+f"(c[2]), "+f"(c[3])
        : "r"(a[0]), "r"(a[1]), "r"(a[2]), "r"(a[3]), "r"(b[0]), "r"(b[1]));
}

// =====================================================================
// GEMM: out[M,512] = A[M,512] @ W[512,512] + bias  (MODE 0)
//       out = res + relu(A@W + bias)               (MODE 1)
// Block tile 128x128x32, 256 threads (8 warps, 2x4), warp tile 64x32.
// =====================================================================
#define SA_STR 40    // 40 % 32 == 8  -> conflict-free A-frag loads
#define SB_STR 136   // 136 % 32 == 8 -> conflict-free B-frag loads

template<int MODE>
__global__ void __launch_bounds__(256)
gemm_tf32(const float* __restrict__ A, const float* __restrict__ W,
          const float* __restrict__ bias, const float* __restrict__ res,
          float* __restrict__ out)
{
    __shared__ unsigned sA[128*SA_STR];
    __shared__ unsigned sB[32*SB_STR];

    const int tid  = threadIdx.x;
    const int warp = tid >> 5, lane = tid & 31;
    const int g = lane >> 2, t = lane & 3;
    const int wm = (warp >> 2) * 64;   // warp m-offset (0/64)
    const int wn = (warp & 3) * 32;    // warp n-offset (0/32/64/96)
    const int bm = blockIdx.x * 128;
    const int bn = blockIdx.y * 128;

    float acc[4][4][4];
    #pragma unroll
    for (int i=0;i<4;i++) for (int j=0;j<4;j++) for (int r=0;r<4;r++) acc[i][j][r]=0.f;

    for (int kt = 0; kt < 512; kt += 32){
        // load A tile 128x32 (tf32-converted)
        #pragma unroll
        for (int i=0;i<4;i++){
            int idx = tid + 256*i;
            int r = idx >> 3, c = (idx & 7) * 4;
            float4 va = *(const float4*)(A + (size_t)(bm + r)*512 + kt + c);
            unsigned* d = &sA[r*SA_STR + c];
            d[0]=f2tf(va.x); d[1]=f2tf(va.y); d[2]=f2tf(va.z); d[3]=f2tf(va.w);
        }
        // load B tile 32x128
        #pragma unroll
        for (int i=0;i<4;i++){
            int idx = tid + 256*i;
            int r = idx >> 5, c = (idx & 31) * 4;
            float4 vb = *(const float4*)(W + (size_t)(kt + r)*512 + bn + c);
            unsigned* d = &sB[r*SB_STR + c];
            d[0]=f2tf(vb.x); d[1]=f2tf(vb.y); d[2]=f2tf(vb.z); d[3]=f2tf(vb.w);
        }
        __syncthreads();

        #pragma unroll
        for (int kk=0; kk<4; kk++){
            unsigned af[4][4], bf[4][2];
            #pragma unroll
            for (int mf=0; mf<4; mf++){
                int rb = wm + mf*16 + g;
                int cb = kk*8 + t;
                af[mf][0] = sA[ rb     *SA_STR + cb    ];
                af[mf][1] = sA[(rb + 8)*SA_STR + cb    ];
                af[mf][2] = sA[ rb     *SA_STR + cb + 4];
                af[mf][3] = sA[(rb + 8)*SA_STR + cb + 4];
            }
            #pragma unroll
            for (int nf=0; nf<4; nf++){
                int cb = wn + nf*8 + g;
                bf[nf][0] = sB[(kk*8 + t    )*SB_STR + cb];
                bf[nf][1] = sB[(kk*8 + t + 4)*SB_STR + cb];
            }
            #pragma unroll
            for (int mf=0; mf<4; mf++)
                #pragma unroll
                for (int nf=0; nf<4; nf++)
                    mma_tf32(acc[mf][nf], af[mf], bf[nf]);
        }
        __syncthreads();
    }

    // epilogue
    #pragma unroll
    for (int mf=0; mf<4; mf++){
        #pragma unroll
        for (int nf=0; nf<4; nf++){
            int row = bm + wm + mf*16 + g;
            int col = bn + wn + nf*8 + 2*t;
            float b0 = bias[col], b1 = bias[col+1];
            float v0 = acc[mf][nf][0] + b0, v1 = acc[mf][nf][1] + b1;
            float v2 = acc[mf][nf][2] + b0, v3 = acc[mf][nf][3] + b1;
            if (MODE == 1){
                float2 r0 = *(const float2*)(res + (size_t)row*512 + col);
                float2 r1 = *(const float2*)(res + (size_t)(row+8)*512 + col);
                v0 = fmaxf(v0, 0.f) + r0.x;  v1 = fmaxf(v1, 0.f) + r0.y;
                v2 = fmaxf(v2, 0.f) + r1.x;  v3 = fmaxf(v3, 0.f) + r1.y;
            }
            *(float2*)(out + (size_t)row*512 + col)      = make_float2(v0, v1);
            *(float2*)(out + (size_t)(row+8)*512 + col)  = make_float2(v2, v3);
        }
    }
}

// =====================================================================
// Flash attention per (b,h): BM=64 queries, BN=128 keys/tile, dh=64.
// 4 warps, each owns 16 full rows (online softmax per warp).
// h0 = softmax(q kT / sqrt(512)) @ v + q    (head slice)
// =====================================================================
#define FA_BM   64
#define FA_BN   128
#define KS_STR  68    // 68 % 32 == 4  -> conflict-free for S B-frags
#define VS_STR  72    // 72 % 32 == 8  -> conflict-free for PV B-frags
#define PS_STR  132   // 132 % 32 == 4 -> conflict-free for PV A-frags
#define FA_SMEM ((128*KS_STR + 128*VS_STR + 64*PS_STR) * 4)

__global__ void __launch_bounds__(128)
flash_kernel(const float* __restrict__ q, const float* __restrict__ k,
             const float* __restrict__ v, float* __restrict__ h0)
{
    extern __shared__ unsigned smem[];
    unsigned* sK = smem;                       // [128][KS_STR]
    unsigned* sV = sK + 128*KS_STR;            // [128][VS_STR]
    unsigned* sP = sV + 128*VS_STR;            // [64][PS_STR]

    const int tid  = threadIdx.x;
    const int warp = tid >> 5, lane = tid & 31;
    const int g = lane >> 2, t = lane & 3;
    const int bh = blockIdx.y;
    const int b  = bh >> 3, h = bh & 7;
    const int m0 = blockIdx.x * FA_BM;

    const size_t qbase = (size_t)b*NQ_*DM + (size_t)h*DH;
    const size_t kbase = (size_t)b*NK_*DM + (size_t)h*DH;
    const float scale = 0.044194173824159216f;   // 1/sqrt(512)

    // ---- Q fragments (held in registers for the whole block) ----
    const int ra = m0 + warp*16 + g;             // global row (within batch)
    unsigned qf[8][4];
    #pragma unroll
    for (int kk=0; kk<8; kk++){
        int c0 = kk*8 + t;
        qf[kk][0] = f2tf(scale * q[qbase + (size_t) ra     *DM + c0    ]);
        qf[kk][1] = f2tf(scale * q[qbase + (size_t)(ra + 8)*DM + c0    ]);
        qf[kk][2] = f2tf(scale * q[qbase + (size_t) ra     *DM + c0 + 4]);
        qf[kk][3] = f2tf(scale * q[qbase + (size_t)(ra + 8)*DM + c0 + 4]);
    }

    float o[8][4];
    #pragma unroll
    for (int i=0;i<8;i++) for (int j=0;j<4;j++) o[i][j]=0.f;
    float m_a = -INFINITY, m_b = -INFINITY, l_a = 0.f, l_b = 0.f;

    for (int kt = 0; kt < NK_; kt += FA_BN){
        __syncthreads();   // protect smem reuse across iterations
        // ---- load K/V tiles (128 keys x 64 dims), tf32-converted ----
        #pragma unroll
        for (int i=0;i<16;i++){
            int idx = tid + 128*i;
            int key = idx >> 4, c = (idx & 15) * 4;
            size_t ga = kbase + (size_t)(kt + key)*DM + c;
            float4 kv = *(const float4*)(k + ga);
            float4 vv = *(const float4*)(v + ga);
            unsigned* dk = &sK[key*KS_STR + c];
            dk[0]=f2tf(kv.x); dk[1]=f2tf(kv.y); dk[2]=f2tf(kv.z); dk[3]=f2tf(kv.w);
            unsigned* dv = &sV[key*VS_STR + c];
            dv[0]=f2tf(vv.x); dv[1]=f2tf(vv.y); dv[2]=f2tf(vv.z); dv[3]=f2tf(vv.w);
        }
        __syncthreads();

        // ---- S = Qh @ Kh^T  (16 x 128 per warp) ----
        float s[16][4];
        #pragma unroll
        for (int i=0;i<16;i++) for (int j=0;j<4;j++) s[i][j]=0.f;
        #pragma unroll
        for (int kk=0; kk<8; kk++){
            #pragma unroll
            for (int nf=0; nf<16; nf++){
                unsigned bb[2];
                bb[0] = sK[(nf*8 + g)*KS_STR + kk*8 + t    ];
                bb[1] = sK[(nf*8 + g)*KS_STR + kk*8 + t + 4];
                mma_tf32(s[nf], qf[kk], bb);
            }
        }

        // ---- online softmax (two rows per thread: g and g+8) ----
        float ma = -INFINITY, mb = -INFINITY;
        #pragma unroll
        for (int nf=0; nf<16; nf++){
            ma = fmaxf(ma, fmaxf(s[nf][0], s[nf][1]));
            mb = fmaxf(mb, fmaxf(s[nf][2], s[nf][3]));
        }
        ma = fmaxf(ma, __shfl_xor_sync(0xffffffffu, ma, 1));
        ma = fmaxf(ma, __shfl_xor_sync(0xffffffffu, ma, 2));
        mb = fmaxf(mb, __shfl_xor_sync(0xffffffffu, mb, 1));
        mb = fmaxf(mb, __shfl_xor_sync(0xffffffffu, mb, 2));
        float mna = fmaxf(m_a, ma), mnb = fmaxf(m_b, mb);
        float alpha_a = __expf(m_a - mna), alpha_b = __expf(m_b - mnb);

        float sa = 0.f, sb = 0.f;
        const int pra = (warp*16 + g)*PS_STR;
        const int prb = pra + 8*PS_STR;
        #pragma unroll
        for (int nf=0; nf<16; nf++){
            float p0 = __expf(s[nf][0] - mna), p1 = __expf(s[nf][1] - mna);
            float p2 = __expf(s[nf][2] - mnb), p3 = __expf(s[nf][3] - mnb);
            sa += p0 + p1;  sb += p2 + p3;
            int c = nf*8 + 2*t;
            sP[pra + c] = f2tf(p0);  sP[pra + c + 1] = f2tf(p1);
            sP[prb + c] = f2tf(p2);  sP[prb + c + 1] = f2tf(p3);
        }
        sa += __shfl_xor_sync(0xffffffffu, sa, 1);
        sa += __shfl_xor_sync(0xffffffffu, sa, 2);
        sb += __shfl_xor_sync(0xffffffffu, sb, 1);
        sb += __shfl_xor_sync(0xffffffffu, sb, 2);
        l_a = l_a*alpha_a + sa;  l_b = l_b*alpha_b + sb;
        m_a = mna;  m_b = mnb;
        #pragma unroll
        for (int nf=0; nf<8; nf++){
            o[nf][0]*=alpha_a; o[nf][1]*=alpha_a; o[nf][2]*=alpha_b; o[nf][3]*=alpha_b;
        }
        __syncwarp();   // sP is per-warp private; warp-level visibility suffices

        // ---- O += P @ Vh  (16 x 64 per warp, K=128) ----
        #pragma unroll
        for (int kk=0; kk<16; kk++){
            unsigned af[4];
            int c0 = kk*8 + t;
            af[0] = sP[pra + c0    ];  af[1] = sP[prb + c0    ];
            af[2] = sP[pra + c0 + 4];  af[3] = sP[prb + c0 + 4];
            #pragma unroll
            for (int nf=0; nf<8; nf++){
                unsigned bb[2];
                bb[0] = sV[(kk*8 + t    )*VS_STR + nf*8 + g];
                bb[1] = sV[(kk*8 + t + 4)*VS_STR + nf*8 + g];
                mma_tf32(o[nf], af, bb);
            }
        }
    }

    // ---- epilogue: normalize + q residual ----
    float ia = 1.f / l_a, ib = 1.f / l_b;
    size_t oa = qbase + (size_t)ra*DM;
    #pragma unroll
    for (int nf=0; nf<8; nf++){
        int c = nf*8 + 2*t;
        float2 q0 = *(const float2*)(q + oa + c);
        float2 q1 = *(const float2*)(q + oa + (size_t)8*DM + c);
        *(float2*)(h0 + oa + c) =
            make_float2(o[nf][0]*ia + q0.x, o[nf][1]*ia + q0.y);
        *(float2*)(h0 + oa + (size_t)8*DM + c) =
            make_float2(o[nf][2]*ib + q1.x, o[nf][3]*ib + q1.y);
    }
}

// =====================================================================
// LayerNorm over last dim (512); one warp per row, 8 rows per block.
// =====================================================================
__global__ void __launch_bounds__(256)
ln_kernel(const float* __restrict__ x, const float* __restrict__ gam,
          const float* __restrict__ bet, float* __restrict__ y)
{
    const int row  = blockIdx.x*8 + (threadIdx.x >> 5);
    const int lane = threadIdx.x & 31;
    const float* xr = x + (size_t)row*DM;

    float4 vv[4];
    float s = 0.f, sq = 0.f;
    #pragma unroll
    for (int i=0;i<4;i++){
        vv[i] = *(const float4*)(xr + (lane + 32*i)*4);
        s  += vv[i].x + vv[i].y + vv[i].z + vv[i].w;
        sq += vv[i].x*vv[i].x + vv[i].y*vv[i].y + vv[i].z*vv[i].z + vv[i].w*vv[i].w;
    }
    #pragma unroll
    for (int off=16; off; off>>=1){
        s  += __shfl_xor_sync(0xffffffffu, s,  off);
        sq += __shfl_xor_sync(0xffffffffu, sq, off);
    }
    float mu  = s * (1.f/512.f);
    float var = sq * (1.f/512.f) - mu*mu;
    float rs  = rsqrtf(var + 1e-5f);

    float* yr = y + (size_t)row*DM;
    #pragma unroll
    for (int i=0;i<4;i++){
        int c = (lane + 32*i)*4;
        float4 gv = *(const float4*)(gam + c);
        float4 bv = *(const float4*)(bet + c);
        float4 ov;
        ov.x = (vv[i].x - mu)*rs*gv.x + bv.x;
        ov.y = (vv[i].y - mu)*rs*gv.y + bv.y;
        ov.z = (vv[i].z - mu)*rs*gv.z + bv.z;
        ov.w = (vv[i].w - mu)*rs*gv.w + bv.w;
        *(float4*)(yr + c) = ov;
    }
}

// =====================================================================
// kernel_launch
// =====================================================================
extern "C" void kernel_launch(void* const* d_in, const int* in_sizes, int n_in,
                              void* d_out, int out_size)
{
    (void)in_sizes; (void)n_in; (void)out_size;
    const float* Q    = (const float*)d_in[0];
    const float* K    = (const float*)d_in[1];
    const float* Wq   = (const float*)d_in[2];
    const float* bq   = (const float*)d_in[3];
    const float* Wk   = (const float*)d_in[4];
    const float* bk   = (const float*)d_in[5];
    const float* Wv   = (const float*)d_in[6];
    const float* bv   = (const float*)d_in[7];
    const float* Wo   = (const float*)d_in[8];
    const float* bo   = (const float*)d_in[9];
    const float* ln0g = (const float*)d_in[10];
    const float* ln0b = (const float*)d_in[11];
    const float* ln1g = (const float*)d_in[12];
    const float* ln1b = (const float*)d_in[13];
    float* out = (float*)d_out;

    float *qb, *kb, *vb, *h0, *h1, *h2;
    cudaGetSymbolAddress((void**)&qb, g_q);
    cudaGetSymbolAddress((void**)&kb, g_k);
    cudaGetSymbolAddress((void**)&vb, g_v);
    cudaGetSymbolAddress((void**)&h0, g_h0);
    cudaGetSymbolAddress((void**)&h1, g_h1);
    cudaGetSymbolAddress((void**)&h2, g_h2);

    cudaFuncSetAttribute(flash_kernel,
        cudaFuncAttributeMaxDynamicSharedMemorySize, FA_SMEM);

    dim3 ggrid(MTOT/128, 512/128);
    // projections
    gemm_tf32<0><<<ggrid, 256>>>(Q, Wq, bq, nullptr, qb);
    gemm_tf32<0><<<ggrid, 256>>>(K, Wk, bk, nullptr, kb);
    gemm_tf32<0><<<ggrid, 256>>>(K, Wv, bv, nullptr, vb);
    // attention + q residual
    flash_kernel<<<dim3(NQ_/FA_BM, B_*NH), 128, FA_SMEM>>>(qb, kb, vb, h0);
    // LN0
    ln_kernel<<<MTOT/8, 256>>>(h0, ln0g, ln0b, h1);
    // FFN: h2 = h1 + relu(h1 Wo + bo)
    gemm_tf32<1><<<ggrid, 256>>>(h1, Wo, bo, h1, h2);
    // LN1 -> output
    ln_kernel<<<MTOT/8, 256>>>(h2, ln1g, ln1b, out);
}

// round 3
// speedup vs baseline: 1.0018x; 1.0018x over previous
#include <cuda_runtime.h>
#include <cstdint>
#include <math.h>

// ---------------- problem constants ----------------
#define B_    4
#define NQ_   2048
#define NK_   2048
#define DM    512
#define NH    8
#define DH    64
#define MTOT  (B_*NQ_)          // 8192 rows

// ---------------- scratch (device globals; no allocations allowed) --------
__device__ float g_q [B_*NQ_*DM];
__device__ float g_k [B_*NK_*DM];
__device__ float g_v [B_*NK_*DM];
__device__ float g_h0[B_*NQ_*DM];   // attention out + q residual (pre-LN0)
__device__ float g_h1[B_*NQ_*DM];   // post-LN0
__device__ float g_h2[B_*NQ_*DM];   // H1 + relu(H1 Wo + bo) (pre-LN1)

// ---------------- tf32 helpers ----------------
__device__ __forceinline__ unsigned f2tf(float x){
    unsigned u; asm("cvt.rna.tf32.f32 %0, %1;" : "=r"(u) : "f"(x)); return u;
}
__device__ __forceinline__ void mma_tf32(float* c, const unsigned* a, const unsigned* b){
    asm volatile("mma.sync.aligned.m16n8k8.row.col.f32.tf32.tf32.f32 "
        "{%0,%1,%2,%3}, {%4,%5,%6,%7}, {%8,%9}, {%0,%1,%2,%3};\n"
        : "+f"(c[0]), "+f"(c[1]), "+f"(c[2]), "+f"(c[3])
        : "r"(a[0]), "r"(a[1]), "r"(a[2]), "r"(a[3]), "r"(b[0]), "r"(b[1]));
}

// =====================================================================
// GEMM: out[M,512] = A[M,512] @ W[512,512] + bias  (MODE 0)
//       out = res + relu(A@W + bias)               (MODE 1)
// Block tile 128x128x32, 256 threads (8 warps, 2x4), warp tile 64x32.
// =====================================================================
#define SA_STR 40    // 40 % 32 == 8  -> conflict-free A-frag loads
#define SB_STR 136   // 136 % 32 == 8 -> conflict-free B-frag loads

template<int MODE>
__global__ void __launch_bounds__(256)
gemm_tf32(const float* __restrict__ A, const float* __restrict__ W,
          const float* __restrict__ bias, const float* __restrict__ res,
          float* __restrict__ out)
{
    __shared__ unsigned sA[128*SA_STR];
    __shared__ unsigned sB[32*SB_STR];

    const int tid  = threadIdx.x;
    const int warp = tid >> 5, lane = tid & 31;
    const int g = lane >> 2, t = lane & 3;
    const int wm = (warp >> 2) * 64;   // warp m-offset (0/64)
    const int wn = (warp & 3) * 32;    // warp n-offset (0/32/64/96)
    const int bm = blockIdx.x * 128;
    const int bn = blockIdx.y * 128;

    float acc[4][4][4];
    #pragma unroll
    for (int i=0;i<4;i++) for (int j=0;j<4;j++) for (int r=0;r<4;r++) acc[i][j][r]=0.f;

    for (int kt = 0; kt < 512; kt += 32){
        // load A tile 128x32 (tf32-converted)
        #pragma unroll
        for (int i=0;i<4;i++){
            int idx = tid + 256*i;
            int r = idx >> 3, c = (idx & 7) * 4;
            float4 va = *(const float4*)(A + (size_t)(bm + r)*512 + kt + c);
            unsigned* d = &sA[r*SA_STR + c];
            d[0]=f2tf(va.x); d[1]=f2tf(va.y); d[2]=f2tf(va.z); d[3]=f2tf(va.w);
        }
        // load B tile 32x128
        #pragma unroll
        for (int i=0;i<4;i++){
            int idx = tid + 256*i;
            int r = idx >> 5, c = (idx & 31) * 4;
            float4 vb = *(const float4*)(W + (size_t)(kt + r)*512 + bn + c);
            unsigned* d = &sB[r*SB_STR + c];
            d[0]=f2tf(vb.x); d[1]=f2tf(vb.y); d[2]=f2tf(vb.z); d[3]=f2tf(vb.w);
        }
        __syncthreads();

        #pragma unroll
        for (int kk=0; kk<4; kk++){
            unsigned af[4][4], bf[4][2];
            #pragma unroll
            for (int mf=0; mf<4; mf++){
                int rb = wm + mf*16 + g;
                int cb = kk*8 + t;
                af[mf][0] = sA[ rb     *SA_STR + cb    ];
                af[mf][1] = sA[(rb + 8)*SA_STR + cb    ];
                af[mf][2] = sA[ rb     *SA_STR + cb + 4];
                af[mf][3] = sA[(rb + 8)*SA_STR + cb + 4];
            }
            #pragma unroll
            for (int nf=0; nf<4; nf++){
                int cb = wn + nf*8 + g;
                bf[nf][0] = sB[(kk*8 + t    )*SB_STR + cb];
                bf[nf][1] = sB[(kk*8 + t + 4)*SB_STR + cb];
            }
            #pragma unroll
            for (int mf=0; mf<4; mf++)
                #pragma unroll
                for (int nf=0; nf<4; nf++)
                    mma_tf32(acc[mf][nf], af[mf], bf[nf]);
        }
        __syncthreads();
    }

    // epilogue
    #pragma unroll
    for (int mf=0; mf<4; mf++){
        #pragma unroll
        for (int nf=0; nf<4; nf++){
            int row = bm + wm + mf*16 + g;
            int col = bn + wn + nf*8 + 2*t;
            float b0 = bias[col], b1 = bias[col+1];
            float v0 = acc[mf][nf][0] + b0, v1 = acc[mf][nf][1] + b1;
            float v2 = acc[mf][nf][2] + b0, v3 = acc[mf][nf][3] + b1;
            if (MODE == 1){
                float2 r0 = *(const float2*)(res + (size_t)row*512 + col);
                float2 r1 = *(const float2*)(res + (size_t)(row+8)*512 + col);
                v0 = fmaxf(v0, 0.f) + r0.x;  v1 = fmaxf(v1, 0.f) + r0.y;
                v2 = fmaxf(v2, 0.f) + r1.x;  v3 = fmaxf(v3, 0.f) + r1.y;
            }
            *(float2*)(out + (size_t)row*512 + col)      = make_float2(v0, v1);
            *(float2*)(out + (size_t)(row+8)*512 + col)  = make_float2(v2, v3);
        }
    }
}

// =====================================================================
// Flash attention per (b,h): BM=64 queries, BN=128 keys/tile, dh=64.
// 4 warps, each owns 16 full rows (online softmax per warp).
// h0 = softmax(q kT / sqrt(512)) @ v + q    (head slice)
// =====================================================================
#define FA_BM   64
#define FA_BN   128
#define KS_STR  68    // 68 % 32 == 4  -> conflict-free for S B-frags
#define VS_STR  72    // 72 % 32 == 8  -> conflict-free for PV B-frags
#define PS_STR  132   // 132 % 32 == 4 -> conflict-free for PV A-frags
#define FA_SMEM ((128*KS_STR + 128*VS_STR + 64*PS_STR) * 4)

__global__ void __launch_bounds__(128)
flash_kernel(const float* __restrict__ q, const float* __restrict__ k,
             const float* __restrict__ v, float* __restrict__ h0)
{
    extern __shared__ unsigned smem[];
    unsigned* sK = smem;                       // [128][KS_STR]
    unsigned* sV = sK + 128*KS_STR;            // [128][VS_STR]
    unsigned* sP = sV + 128*VS_STR;            // [64][PS_STR]

    const int tid  = threadIdx.x;
    const int warp = tid >> 5, lane = tid & 31;
    const int g = lane >> 2, t = lane & 3;
    const int bh = blockIdx.y;
    const int b  = bh >> 3, h = bh & 7;
    const int m0 = blockIdx.x * FA_BM;

    const size_t qbase = (size_t)b*NQ_*DM + (size_t)h*DH;
    const size_t kbase = (size_t)b*NK_*DM + (size_t)h*DH;
    const float scale = 0.044194173824159216f;   // 1/sqrt(512)

    // ---- Q fragments (held in registers for the whole block) ----
    const int ra = m0 + warp*16 + g;             // global row (within batch)
    unsigned qf[8][4];
    #pragma unroll
    for (int kk=0; kk<8; kk++){
        int c0 = kk*8 + t;
        qf[kk][0] = f2tf(scale * q[qbase + (size_t) ra     *DM + c0    ]);
        qf[kk][1] = f2tf(scale * q[qbase + (size_t)(ra + 8)*DM + c0    ]);
        qf[kk][2] = f2tf(scale * q[qbase + (size_t) ra     *DM + c0 + 4]);
        qf[kk][3] = f2tf(scale * q[qbase + (size_t)(ra + 8)*DM + c0 + 4]);
    }

    float o[8][4];
    #pragma unroll
    for (int i=0;i<8;i++) for (int j=0;j<4;j++) o[i][j]=0.f;
    float m_a = -INFINITY, m_b = -INFINITY, l_a = 0.f, l_b = 0.f;

    for (int kt = 0; kt < NK_; kt += FA_BN){
        __syncthreads();   // protect smem reuse across iterations
        // ---- load K/V tiles (128 keys x 64 dims), tf32-converted ----
        #pragma unroll
        for (int i=0;i<16;i++){
            int idx = tid + 128*i;
            int key = idx >> 4, c = (idx & 15) * 4;
            size_t ga = kbase + (size_t)(kt + key)*DM + c;
            float4 kv = *(const float4*)(k + ga);
            float4 vv = *(const float4*)(v + ga);
            unsigned* dk = &sK[key*KS_STR + c];
            dk[0]=f2tf(kv.x); dk[1]=f2tf(kv.y); dk[2]=f2tf(kv.z); dk[3]=f2tf(kv.w);
            unsigned* dv = &sV[key*VS_STR + c];
            dv[0]=f2tf(vv.x); dv[1]=f2tf(vv.y); dv[2]=f2tf(vv.z); dv[3]=f2tf(vv.w);
        }
        __syncthreads();

        // ---- S = Qh @ Kh^T  (16 x 128 per warp) ----
        float s[16][4];
        #pragma unroll
        for (int i=0;i<16;i++) for (int j=0;j<4;j++) s[i][j]=0.f;
        #pragma unroll
        for (int kk=0; kk<8; kk++){
            #pragma unroll
            for (int nf=0; nf<16; nf++){
                unsigned bb[2];
                bb[0] = sK[(nf*8 + g)*KS_STR + kk*8 + t    ];
                bb[1] = sK[(nf*8 + g)*KS_STR + kk*8 + t + 4];
                mma_tf32(s[nf], qf[kk], bb);
            }
        }

        // ---- online softmax (two rows per thread: g and g+8) ----
        float ma = -INFINITY, mb = -INFINITY;
        #pragma unroll
        for (int nf=0; nf<16; nf++){
            ma = fmaxf(ma, fmaxf(s[nf][0], s[nf][1]));
            mb = fmaxf(mb, fmaxf(s[nf][2], s[nf][3]));
        }
        ma = fmaxf(ma, __shfl_xor_sync(0xffffffffu, ma, 1));
        ma = fmaxf(ma, __shfl_xor_sync(0xffffffffu, ma, 2));
        mb = fmaxf(mb, __shfl_xor_sync(0xffffffffu, mb, 1));
        mb = fmaxf(mb, __shfl_xor_sync(0xffffffffu, mb, 2));
        float mna = fmaxf(m_a, ma), mnb = fmaxf(m_b, mb);
        float alpha_a = __expf(m_a - mna), alpha_b = __expf(m_b - mnb);

        float sa = 0.f, sb = 0.f;
        const int pra = (warp*16 + g)*PS_STR;
        const int prb = pra + 8*PS_STR;
        #pragma unroll
        for (int nf=0; nf<16; nf++){
            float p0 = __expf(s[nf][0] - mna), p1 = __expf(s[nf][1] - mna);
            float p2 = __expf(s[nf][2] - mnb), p3 = __expf(s[nf][3] - mnb);
            sa += p0 + p1;  sb += p2 + p3;
            int c = nf*8 + 2*t;
            sP[pra + c] = f2tf(p0);  sP[pra + c + 1] = f2tf(p1);
            sP[prb + c] = f2tf(p2);  sP[prb + c + 1] = f2tf(p3);
        }
        sa += __shfl_xor_sync(0xffffffffu, sa, 1);
        sa += __shfl_xor_sync(0xffffffffu, sa, 2);
        sb += __shfl_xor_sync(0xffffffffu, sb, 1);
        sb += __shfl_xor_sync(0xffffffffu, sb, 2);
        l_a = l_a*alpha_a + sa;  l_b = l_b*alpha_b + sb;
        m_a = mna;  m_b = mnb;
        #pragma unroll
        for (int nf=0; nf<8; nf++){
            o[nf][0]*=alpha_a; o[nf][1]*=alpha_a; o[nf][2]*=alpha_b; o[nf][3]*=alpha_b;
        }
        __syncwarp();   // sP is per-warp private; warp-level visibility suffices

        // ---- O += P @ Vh  (16 x 64 per warp, K=128) ----
        #pragma unroll
        for (int kk=0; kk<16; kk++){
            unsigned af[4];
            int c0 = kk*8 + t;
            af[0] = sP[pra + c0    ];  af[1] = sP[prb + c0    ];
            af[2] = sP[pra + c0 + 4];  af[3] = sP[prb + c0 + 4];
            #pragma unroll
            for (int nf=0; nf<8; nf++){
                unsigned bb[2];
                bb[0] = sV[(kk*8 + t    )*VS_STR + nf*8 + g];
                bb[1] = sV[(kk*8 + t + 4)*VS_STR + nf*8 + g];
                mma_tf32(o[nf], af, bb);
            }
        }
    }

    // ---- epilogue: normalize + q residual ----
    float ia = 1.f / l_a, ib = 1.f / l_b;
    size_t oa = qbase + (size_t)ra*DM;
    #pragma unroll
    for (int nf=0; nf<8; nf++){
        int c = nf*8 + 2*t;
        float2 q0 = *(const float2*)(q + oa + c);
        float2 q1 = *(const float2*)(q + oa + (size_t)8*DM + c);
        *(float2*)(h0 + oa + c) =
            make_float2(o[nf][0]*ia + q0.x, o[nf][1]*ia + q0.y);
        *(float2*)(h0 + oa + (size_t)8*DM + c) =
            make_float2(o[nf][2]*ib + q1.x, o[nf][3]*ib + q1.y);
    }
}

// =====================================================================
// LayerNorm over last dim (512); one warp per row, 8 rows per block.
// =====================================================================
__global__ void __launch_bounds__(256)
ln_kernel(const float* __restrict__ x, const float* __restrict__ gam,
          const float* __restrict__ bet, float* __restrict__ y)
{
    const int row  = blockIdx.x*8 + (threadIdx.x >> 5);
    const int lane = threadIdx.x & 31;
    const float* xr = x + (size_t)row*DM;

    float4 vv[4];
    float s = 0.f, sq = 0.f;
    #pragma unroll
    for (int i=0;i<4;i++){
        vv[i] = *(const float4*)(xr + (lane + 32*i)*4);
        s  += vv[i].x + vv[i].y + vv[i].z + vv[i].w;
        sq += vv[i].x*vv[i].x + vv[i].y*vv[i].y + vv[i].z*vv[i].z + vv[i].w*vv[i].w;
    }
    #pragma unroll
    for (int off=16; off; off>>=1){
        s  += __shfl_xor_sync(0xffffffffu, s,  off);
        sq += __shfl_xor_sync(0xffffffffu, sq, off);
    }
    float mu  = s * (1.f/512.f);
    float var = sq * (1.f/512.f) - mu*mu;
    float rs  = rsqrtf(var + 1e-5f);

    float* yr = y + (size_t)row*DM;
    #pragma unroll
    for (int i=0;i<4;i++){
        int c = (lane + 32*i)*4;
        float4 gv = *(const float4*)(gam + c);
        float4 bv = *(const float4*)(bet + c);
        float4 ov;
        ov.x = (vv[i].x - mu)*rs*gv.x + bv.x;
        ov.y = (vv[i].y - mu)*rs*gv.y + bv.y;
        ov.z = (vv[i].z - mu)*rs*gv.z + bv.z;
        ov.w = (vv[i].w - mu)*rs*gv.w + bv.w;
        *(float4*)(yr + c) = ov;
    }
}

// =====================================================================
// kernel_launch
// =====================================================================
extern "C" void kernel_launch(void* const* d_in, const int* in_sizes, int n_in,
                              void* d_out, int out_size)
{
    (void)in_sizes; (void)n_in; (void)out_size;
    const float* Q    = (const float*)d_in[0];
    const float* K    = (const float*)d_in[1];
    const float* Wq   = (const float*)d_in[2];
    const float* bq   = (const float*)d_in[3];
    const float* Wk   = (const float*)d_in[4];
    const float* bk   = (const float*)d_in[5];
    const float* Wv   = (const float*)d_in[6];
    const float* bv   = (const float*)d_in[7];
    const float* Wo   = (const float*)d_in[8];
    const float* bo   = (const float*)d_in[9];
    const float* ln0g = (const float*)d_in[10];
    const float* ln0b = (const float*)d_in[11];
    const float* ln1g = (const float*)d_in[12];
    const float* ln1b = (const float*)d_in[13];
    float* out = (float*)d_out;

    float *qb, *kb, *vb, *h0, *h1, *h2;
    cudaGetSymbolAddress((void**)&qb, g_q);
    cudaGetSymbolAddress((void**)&kb, g_k);
    cudaGetSymbolAddress((void**)&vb, g_v);
    cudaGetSymbolAddress((void**)&h0, g_h0);
    cudaGetSymbolAddress((void**)&h1, g_h1);
    cudaGetSymbolAddress((void**)&h2, g_h2);

    cudaFuncSetAttribute(flash_kernel,
        cudaFuncAttributeMaxDynamicSharedMemorySize, FA_SMEM);

    dim3 ggrid(MTOT/128, 512/128);
    // projections
    gemm_tf32<0><<<ggrid, 256>>>(Q, Wq, bq, nullptr, qb);
    gemm_tf32<0><<<ggrid, 256>>>(K, Wk, bk, nullptr, kb);
    gemm_tf32<0><<<ggrid, 256>>>(K, Wv, bv, nullptr, vb);
    // attention + q residual
    flash_kernel<<<dim3(NQ_/FA_BM, B_*NH), 128, FA_SMEM>>>(qb, kb, vb, h0);
    // LN0
    ln_kernel<<<MTOT/8, 256>>>(h0, ln0g, ln0b, h1);
    // FFN: h2 = h1 + relu(h1 Wo + bo)
    gemm_tf32<1><<<ggrid, 256>>>(h1, Wo, bo, h1, h2);
    // LN1 -> output
    ln_kernel<<<MTOT/8, 256>>>(h2, ln1g, ln1b, out);
}